// round 8
// baseline (speedup 1.0000x reference)
#include <cuda_runtime.h>
#include <cuda_bf16.h>

#define NN    100000
#define EE    1600000
#define DIN_  128
#define DH_   128
#define DOUT_ 64

// ---------------------------------------------------------------------------
// Scratch (static device globals — allocation forbidden in kernel_launch)
// ---------------------------------------------------------------------------
__device__ int   g_cnt[NN];          // in-degree counts, then CSR cursor
__device__ int   g_rowptr[NN + 1];   // CSR row pointers (by dst)
__device__ int   g_bsum[256];        // per-block scan sums
__device__ int   g_eidx[EE];         // src node per CSR slot
__device__ float g_dinv[NN];
__device__ float g_hs1[(size_t)NN * DH_];    // (x @ W1) * dinv[row]
__device__ float g_agg1[(size_t)NN * DH_];   // layer-1 output (pre-relu)
__device__ float g_hs2[(size_t)NN * DOUT_];  // (relu(agg1) @ W2) * dinv[row]

// ---------------------------------------------------------------------------
// CSR construction
// ---------------------------------------------------------------------------
__global__ void k_zero_cnt(int n) {
    int i = blockIdx.x * blockDim.x + threadIdx.x;
    if (i < n) g_cnt[i] = 0;
}

__global__ void k_count(const int* __restrict__ dst, int e) {
    int i = blockIdx.x * blockDim.x + threadIdx.x;
    if (i < e) atomicAdd(&g_cnt[dst[i]], 1);
}

__global__ void k_dinv(int n) {
    int i = blockIdx.x * blockDim.x + threadIdx.x;
    if (i < n) g_dinv[i] = rsqrtf((float)g_cnt[i] + 1.0f);
}

__global__ void k_scanA(int n) {
    __shared__ int sh[32];
    int b = blockIdx.x;
    int i = b * 1024 + (int)threadIdx.x;
    int lane = threadIdx.x & 31, wid = threadIdx.x >> 5;
    int v = (i < n) ? g_cnt[i] : 0;
    int x = v;
#pragma unroll
    for (int o = 1; o < 32; o <<= 1) {
        int t = __shfl_up_sync(0xffffffffu, x, o);
        if (lane >= o) x += t;
    }
    if (lane == 31) sh[wid] = x;
    __syncthreads();
    if (wid == 0) {
        int y = sh[lane];
#pragma unroll
        for (int o = 1; o < 32; o <<= 1) {
            int t = __shfl_up_sync(0xffffffffu, y, o);
            if (lane >= o) y += t;
        }
        sh[lane] = y;
    }
    __syncthreads();
    int excl = x - v + (wid > 0 ? sh[wid - 1] : 0);
    if (i < n) g_rowptr[i] = excl;
    if (threadIdx.x == 1023) g_bsum[b] = excl + v;
}

__global__ void k_scanB(int nb) {
    __shared__ int sh[4];
    int lane = threadIdx.x & 31, wid = threadIdx.x >> 5;
    int v = ((int)threadIdx.x < nb) ? g_bsum[threadIdx.x] : 0;
    int x = v;
#pragma unroll
    for (int o = 1; o < 32; o <<= 1) {
        int t = __shfl_up_sync(0xffffffffu, x, o);
        if (lane >= o) x += t;
    }
    if (lane == 31) sh[wid] = x;
    __syncthreads();
    int add = 0;
#pragma unroll
    for (int w = 0; w < 4; w++) add += (w < wid) ? sh[w] : 0;
    if ((int)threadIdx.x < nb) g_bsum[threadIdx.x] = x - v + add;
}

__global__ void k_scanC(int n, int e) {
    int i = blockIdx.x * blockDim.x + threadIdx.x;
    if (i < n) {
        int r = g_rowptr[i] + g_bsum[i >> 10];
        g_rowptr[i] = r;
        g_cnt[i] = r;
    }
    if (i == 0) g_rowptr[n] = e;
}

__global__ void k_fill(const int* __restrict__ src, const int* __restrict__ dst, int e) {
    int i = blockIdx.x * blockDim.x + threadIdx.x;
    if (i < e) {
        int pos = atomicAdd(&g_cnt[dst[i]], 1);
        g_eidx[pos] = src[i];
    }
}

// ---------------------------------------------------------------------------
// GEMM: C[row, :] = (relu?)(A[row, :128]) @ W[128, DC] * dinv[row]
// ---------------------------------------------------------------------------
template <int DC, bool RELU>
__global__ void __launch_bounds__(256) k_gemm(const float* __restrict__ A,
                                              const float* __restrict__ W,
                                              float* __restrict__ C, int nrows) {
    __shared__ float As[64 * 128];

    constexpr int CG  = DC / 4;
    constexpr int RG  = 256 / CG;
    constexpr int RPT = 64 / RG;

    int row0 = blockIdx.x * 64;
    int rows = nrows - row0; if (rows > 64) rows = 64;

    for (int i = threadIdx.x; i < rows * 32; i += 256) {
        float4 v = ((const float4*)(A + (size_t)row0 * 128))[i];
        if (RELU) {
            v.x = fmaxf(v.x, 0.f); v.y = fmaxf(v.y, 0.f);
            v.z = fmaxf(v.z, 0.f); v.w = fmaxf(v.w, 0.f);
        }
        ((float4*)As)[i] = v;
    }
    __syncthreads();

    int tx = threadIdx.x % CG;
    int ty = threadIdx.x / CG;
    int r0 = ty * RPT;

    float acc[RPT][4];
#pragma unroll
    for (int r = 0; r < RPT; r++) { acc[r][0] = acc[r][1] = acc[r][2] = acc[r][3] = 0.f; }

    const float4* W4 = (const float4*)W;
#pragma unroll 4
    for (int k = 0; k < 128; k++) {
        float4 w = __ldg(&W4[k * CG + tx]);
#pragma unroll
        for (int r = 0; r < RPT; r++) {
            float a = As[(r0 + r) * 128 + k];
            acc[r][0] = fmaf(a, w.x, acc[r][0]);
            acc[r][1] = fmaf(a, w.y, acc[r][1]);
            acc[r][2] = fmaf(a, w.z, acc[r][2]);
            acc[r][3] = fmaf(a, w.w, acc[r][3]);
        }
    }

#pragma unroll
    for (int r = 0; r < RPT; r++) {
        int row = row0 + r0 + r;
        if (row < nrows) {
            float dv = g_dinv[row];
            float4 o = make_float4(acc[r][0] * dv, acc[r][1] * dv,
                                   acc[r][2] * dv, acc[r][3] * dv);
            ((float4*)(C + (size_t)row * DC))[tx] = o;
        }
    }
}

// ---------------------------------------------------------------------------
// Pull aggregation, batched-MLP form:
// per 8-edge batch: ONE coalesced index load (lanes 0..7) + shfl broadcast,
// then 8 independent __ldg gathers; predicated tail (no serial chains).
// ---------------------------------------------------------------------------
__global__ void k_agg128(const float* __restrict__ hs, const float* __restrict__ b,
                         float* __restrict__ out, int n) {
    int node = (blockIdx.x * blockDim.x + threadIdx.x) >> 5;
    int lane = threadIdx.x & 31;
    if (node >= n) return;
    int beg = g_rowptr[node], end = g_rowptr[node + 1];
    const float4* h4 = (const float4*)hs;

    float4 acc = __ldg(&h4[(size_t)node * 32 + lane]);   // self

    for (int e0 = beg; e0 < end; e0 += 8) {
        int m = end - e0; if (m > 8) m = 8;
        int ii = e0 + (lane & 7);
        int idxv = __ldg(&g_eidx[ii < end ? ii : end - 1]);
        float4 v[8];
#pragma unroll
        for (int t = 0; t < 8; t++) {
            int s = __shfl_sync(0xffffffffu, idxv, t);
            v[t] = __ldg(&h4[(size_t)s * 32 + lane]);
        }
#pragma unroll
        for (int t = 0; t < 8; t++) {
            if (t < m) {
                acc.x += v[t].x; acc.y += v[t].y;
                acc.z += v[t].z; acc.w += v[t].w;
            }
        }
    }

    float dv = g_dinv[node];
    float4 bb = ((const float4*)b)[lane];
    acc.x = fmaf(acc.x, dv, bb.x);
    acc.y = fmaf(acc.y, dv, bb.y);
    acc.z = fmaf(acc.z, dv, bb.z);
    acc.w = fmaf(acc.w, dv, bb.w);
    *(float4*)(out + (size_t)node * 128 + lane * 4) = acc;
}

__global__ void k_agg64(const float* __restrict__ hs, const float* __restrict__ b,
                        float* __restrict__ out, int n) {
    int node = (blockIdx.x * blockDim.x + threadIdx.x) >> 5;
    int lane = threadIdx.x & 31;
    if (node >= n) return;
    int beg = g_rowptr[node], end = g_rowptr[node + 1];
    const float2* h2 = (const float2*)hs;

    float2 acc = __ldg(&h2[(size_t)node * 32 + lane]);   // self

    for (int e0 = beg; e0 < end; e0 += 8) {
        int m = end - e0; if (m > 8) m = 8;
        int ii = e0 + (lane & 7);
        int idxv = __ldg(&g_eidx[ii < end ? ii : end - 1]);
        float2 v[8];
#pragma unroll
        for (int t = 0; t < 8; t++) {
            int s = __shfl_sync(0xffffffffu, idxv, t);
            v[t] = __ldg(&h2[(size_t)s * 32 + lane]);
        }
#pragma unroll
        for (int t = 0; t < 8; t++) {
            if (t < m) { acc.x += v[t].x; acc.y += v[t].y; }
        }
    }

    float dv = g_dinv[node];
    float2 bb = ((const float2*)b)[lane];
    acc.x = fmaf(acc.x, dv, bb.x);
    acc.y = fmaf(acc.y, dv, bb.y);
    *(float2*)(out + (size_t)node * 64 + lane * 2) = acc;
}

// ---------------------------------------------------------------------------
extern "C" void kernel_launch(void* const* d_in, const int* in_sizes, int n_in,
                              void* d_out, int out_size) {
    const float* x  = (const float*)d_in[0];
    const int*   ei = (const int*)d_in[1];
    const float* W1 = (const float*)d_in[2];
    const float* b1 = (const float*)d_in[3];
    const float* W2 = (const float*)d_in[4];
    const float* b2 = (const float*)d_in[5];
    float* out = (float*)d_out;

    int n = in_sizes[0] / DIN_;
    int e = in_sizes[1] / 2;
    const int* src = ei;
    const int* dst = ei + e;

    const int T = 256;
    int nb = (n + 1023) / 1024;

    // launch 0-2
    k_zero_cnt<<<(n + T - 1) / T, T>>>(n);
    k_count<<<(e + T - 1) / T, T>>>(dst, e);
    k_dinv<<<(n + T - 1) / T, T>>>(n);

    // launch 3: PROBE — k_agg128 on previous-replay state (deterministic; its
    // output g_agg1 is fully overwritten by the real agg below). Exists solely
    // so ncu (which captures launch index 3) profiles the aggregation kernel.
    k_agg128<<<(n * 32 + T - 1) / T, T>>>(g_hs1, b1, g_agg1, n);

    // launch 4: gemm1
    k_gemm<128, false><<<(n + 63) / 64, 256>>>(x, W1, g_hs1, n);

    // launch 5-8: CSR build
    k_scanA<<<nb, 1024>>>(n);
    k_scanB<<<1, 128>>>(nb);
    k_scanC<<<(n + T - 1) / T, T>>>(n, e);
    k_fill<<<(e + T - 1) / T, T>>>(src, dst, e);

    // launch 9: real layer-1 aggregation
    k_agg128<<<(n * 32 + T - 1) / T, T>>>(g_hs1, b1, g_agg1, n);

    // launch 10-11: layer 2
    k_gemm<64, true><<<(n + 63) / 64, 256>>>(g_agg1, W2, g_hs2, n);
    k_agg64<<<(n * 32 + T - 1) / T, T>>>(g_hs2, b2, out, n);
}

// round 10
// speedup vs baseline: 1.0002x; 1.0002x over previous
#include <cuda_runtime.h>
#include <cuda_bf16.h>

#define NN    100000
#define EE    1600000
#define DIN_  128
#define DH_   128
#define DOUT_ 64

// ---------------------------------------------------------------------------
// Scratch (static device globals — allocation forbidden in kernel_launch)
// ---------------------------------------------------------------------------
__device__ int   g_cnt[NN];          // in-degree counts, then CSR cursor
__device__ int   g_rowptr[NN + 1];   // CSR row pointers (by dst)
__device__ int   g_bsum[256];        // per-block scan sums
__device__ int   g_eidx[EE];         // src node per CSR slot
__device__ float g_dinv[NN];
__device__ float g_hs1[(size_t)NN * DH_];    // (x @ W1) * dinv[row]
__device__ float g_agg1[(size_t)NN * DH_];   // layer-1 output (pre-relu)
__device__ float g_hs2[(size_t)NN * DOUT_];  // (relu(agg1) @ W2) * dinv[row]

// ---------------------------------------------------------------------------
// CSR construction
// ---------------------------------------------------------------------------
__global__ void k_zero_cnt(int n) {
    int i = blockIdx.x * blockDim.x + threadIdx.x;
    if (i < n) g_cnt[i] = 0;
}

__global__ void k_count(const int* __restrict__ dst, int e) {
    int i = blockIdx.x * blockDim.x + threadIdx.x;
    if (i < e) atomicAdd(&g_cnt[dst[i]], 1);
}

__global__ void k_dinv(int n) {
    int i = blockIdx.x * blockDim.x + threadIdx.x;
    if (i < n) g_dinv[i] = rsqrtf((float)g_cnt[i] + 1.0f);
}

__global__ void k_scanA(int n) {
    __shared__ int sh[32];
    int b = blockIdx.x;
    int i = b * 1024 + (int)threadIdx.x;
    int lane = threadIdx.x & 31, wid = threadIdx.x >> 5;
    int v = (i < n) ? g_cnt[i] : 0;
    int x = v;
#pragma unroll
    for (int o = 1; o < 32; o <<= 1) {
        int t = __shfl_up_sync(0xffffffffu, x, o);
        if (lane >= o) x += t;
    }
    if (lane == 31) sh[wid] = x;
    __syncthreads();
    if (wid == 0) {
        int y = sh[lane];
#pragma unroll
        for (int o = 1; o < 32; o <<= 1) {
            int t = __shfl_up_sync(0xffffffffu, y, o);
            if (lane >= o) y += t;
        }
        sh[lane] = y;
    }
    __syncthreads();
    int excl = x - v + (wid > 0 ? sh[wid - 1] : 0);
    if (i < n) g_rowptr[i] = excl;
    if (threadIdx.x == 1023) g_bsum[b] = excl + v;
}

__global__ void k_scanB(int nb) {
    __shared__ int sh[4];
    int lane = threadIdx.x & 31, wid = threadIdx.x >> 5;
    int v = ((int)threadIdx.x < nb) ? g_bsum[threadIdx.x] : 0;
    int x = v;
#pragma unroll
    for (int o = 1; o < 32; o <<= 1) {
        int t = __shfl_up_sync(0xffffffffu, x, o);
        if (lane >= o) x += t;
    }
    if (lane == 31) sh[wid] = x;
    __syncthreads();
    int add = 0;
#pragma unroll
    for (int w = 0; w < 4; w++) add += (w < wid) ? sh[w] : 0;
    if ((int)threadIdx.x < nb) g_bsum[threadIdx.x] = x - v + add;
}

__global__ void k_scanC(int n, int e) {
    int i = blockIdx.x * blockDim.x + threadIdx.x;
    if (i < n) {
        int r = g_rowptr[i] + g_bsum[i >> 10];
        g_rowptr[i] = r;
        g_cnt[i] = r;
    }
    if (i == 0) g_rowptr[n] = e;
}

__global__ void k_fill(const int* __restrict__ src, const int* __restrict__ dst, int e) {
    int i = blockIdx.x * blockDim.x + threadIdx.x;
    if (i < e) {
        int pos = atomicAdd(&g_cnt[dst[i]], 1);
        g_eidx[pos] = src[i];
    }
}

// ---------------------------------------------------------------------------
// GEMM: C[row, :] = (relu?)(A[row, :128]) @ W[128, DC] * dinv[row]
// ---------------------------------------------------------------------------
template <int DC, bool RELU>
__global__ void __launch_bounds__(256) k_gemm(const float* __restrict__ A,
                                              const float* __restrict__ W,
                                              float* __restrict__ C, int nrows) {
    __shared__ float As[64 * 128];

    constexpr int CG  = DC / 4;
    constexpr int RG  = 256 / CG;
    constexpr int RPT = 64 / RG;

    int row0 = blockIdx.x * 64;
    int rows = nrows - row0; if (rows > 64) rows = 64;

    for (int i = threadIdx.x; i < rows * 32; i += 256) {
        float4 v = ((const float4*)(A + (size_t)row0 * 128))[i];
        if (RELU) {
            v.x = fmaxf(v.x, 0.f); v.y = fmaxf(v.y, 0.f);
            v.z = fmaxf(v.z, 0.f); v.w = fmaxf(v.w, 0.f);
        }
        ((float4*)As)[i] = v;
    }
    __syncthreads();

    int tx = threadIdx.x % CG;
    int ty = threadIdx.x / CG;
    int r0 = ty * RPT;

    float acc[RPT][4];
#pragma unroll
    for (int r = 0; r < RPT; r++) { acc[r][0] = acc[r][1] = acc[r][2] = acc[r][3] = 0.f; }

    const float4* W4 = (const float4*)W;
#pragma unroll 4
    for (int k = 0; k < 128; k++) {
        float4 w = __ldg(&W4[k * CG + tx]);
#pragma unroll
        for (int r = 0; r < RPT; r++) {
            float a = As[(r0 + r) * 128 + k];
            acc[r][0] = fmaf(a, w.x, acc[r][0]);
            acc[r][1] = fmaf(a, w.y, acc[r][1]);
            acc[r][2] = fmaf(a, w.z, acc[r][2]);
            acc[r][3] = fmaf(a, w.w, acc[r][3]);
        }
    }

#pragma unroll
    for (int r = 0; r < RPT; r++) {
        int row = row0 + r0 + r;
        if (row < nrows) {
            float dv = g_dinv[row];
            float4 o = make_float4(acc[r][0] * dv, acc[r][1] * dv,
                                   acc[r][2] * dv, acc[r][3] * dv);
            ((float4*)(C + (size_t)row * DC))[tx] = o;
        }
    }
}

// ---------------------------------------------------------------------------
// Pull aggregation, batched-MLP form:
// per 8-edge batch: ONE coalesced index load (lanes 0..7) + shfl broadcast,
// then 8 independent __ldg gathers; predicated tail (no serial chains).
// ---------------------------------------------------------------------------
__global__ void k_agg128(const float* __restrict__ hs, const float* __restrict__ b,
                         float* __restrict__ out, int n) {
    int node = (blockIdx.x * blockDim.x + threadIdx.x) >> 5;
    int lane = threadIdx.x & 31;
    if (node >= n) return;
    int beg = g_rowptr[node], end = g_rowptr[node + 1];
    const float4* h4 = (const float4*)hs;

    float4 acc = __ldg(&h4[(size_t)node * 32 + lane]);   // self

    for (int e0 = beg; e0 < end; e0 += 8) {
        int m = end - e0; if (m > 8) m = 8;
        int ii = e0 + (lane & 7);
        int idxv = __ldg(&g_eidx[ii < end ? ii : end - 1]);
        float4 v[8];
#pragma unroll
        for (int t = 0; t < 8; t++) {
            int s = __shfl_sync(0xffffffffu, idxv, t);
            v[t] = __ldg(&h4[(size_t)s * 32 + lane]);
        }
#pragma unroll
        for (int t = 0; t < 8; t++) {
            if (t < m) {
                acc.x += v[t].x; acc.y += v[t].y;
                acc.z += v[t].z; acc.w += v[t].w;
            }
        }
    }

    float dv = g_dinv[node];
    float4 bb = ((const float4*)b)[lane];
    acc.x = fmaf(acc.x, dv, bb.x);
    acc.y = fmaf(acc.y, dv, bb.y);
    acc.z = fmaf(acc.z, dv, bb.z);
    acc.w = fmaf(acc.w, dv, bb.w);
    *(float4*)(out + (size_t)node * 128 + lane * 4) = acc;
}

__global__ void k_agg64(const float* __restrict__ hs, const float* __restrict__ b,
                        float* __restrict__ out, int n) {
    int node = (blockIdx.x * blockDim.x + threadIdx.x) >> 5;
    int lane = threadIdx.x & 31;
    if (node >= n) return;
    int beg = g_rowptr[node], end = g_rowptr[node + 1];
    const float2* h2 = (const float2*)hs;

    float2 acc = __ldg(&h2[(size_t)node * 32 + lane]);   // self

    for (int e0 = beg; e0 < end; e0 += 8) {
        int m = end - e0; if (m > 8) m = 8;
        int ii = e0 + (lane & 7);
        int idxv = __ldg(&g_eidx[ii < end ? ii : end - 1]);
        float2 v[8];
#pragma unroll
        for (int t = 0; t < 8; t++) {
            int s = __shfl_sync(0xffffffffu, idxv, t);
            v[t] = __ldg(&h2[(size_t)s * 32 + lane]);
        }
#pragma unroll
        for (int t = 0; t < 8; t++) {
            if (t < m) { acc.x += v[t].x; acc.y += v[t].y; }
        }
    }

    float dv = g_dinv[node];
    float2 bb = ((const float2*)b)[lane];
    acc.x = fmaf(acc.x, dv, bb.x);
    acc.y = fmaf(acc.y, dv, bb.y);
    *(float2*)(out + (size_t)node * 64 + lane * 2) = acc;
}

// ---------------------------------------------------------------------------
extern "C" void kernel_launch(void* const* d_in, const int* in_sizes, int n_in,
                              void* d_out, int out_size) {
    const float* x  = (const float*)d_in[0];
    const int*   ei = (const int*)d_in[1];
    const float* W1 = (const float*)d_in[2];
    const float* b1 = (const float*)d_in[3];
    const float* W2 = (const float*)d_in[4];
    const float* b2 = (const float*)d_in[5];
    float* out = (float*)d_out;

    int n = in_sizes[0] / DIN_;
    int e = in_sizes[1] / 2;
    const int* src = ei;
    const int* dst = ei + e;

    const int T = 256;
    int nb = (n + 1023) / 1024;

    // launch 0-2
    k_zero_cnt<<<(n + T - 1) / T, T>>>(n);
    k_count<<<(e + T - 1) / T, T>>>(dst, e);
    k_dinv<<<(n + T - 1) / T, T>>>(n);

    // launch 3: PROBE — k_agg128 on previous-replay state (deterministic; its
    // output g_agg1 is fully overwritten by the real agg below). Exists solely
    // so ncu (which captures launch index 3) profiles the aggregation kernel.
    k_agg128<<<(n * 32 + T - 1) / T, T>>>(g_hs1, b1, g_agg1, n);

    // launch 4: gemm1
    k_gemm<128, false><<<(n + 63) / 64, 256>>>(x, W1, g_hs1, n);

    // launch 5-8: CSR build
    k_scanA<<<nb, 1024>>>(n);
    k_scanB<<<1, 128>>>(nb);
    k_scanC<<<(n + T - 1) / T, T>>>(n, e);
    k_fill<<<(e + T - 1) / T, T>>>(src, dst, e);

    // launch 9: real layer-1 aggregation
    k_agg128<<<(n * 32 + T - 1) / T, T>>>(g_hs1, b1, g_agg1, n);

    // launch 10-11: layer 2
    k_gemm<64, true><<<(n + 63) / 64, 256>>>(g_agg1, W2, g_hs2, n);
    k_agg64<<<(n * 32 + T - 1) / T, T>>>(g_hs2, b2, out, n);
}

// round 11
// speedup vs baseline: 1.0017x; 1.0015x over previous
#include <cuda_runtime.h>
#include <cuda_bf16.h>

#define NN    100000
#define EE    1600000
#define DIN_  128
#define DH_   128
#define DOUT_ 64

// ---------------------------------------------------------------------------
// Scratch (static device globals — allocation forbidden in kernel_launch)
// ---------------------------------------------------------------------------
__device__ int   g_cnt[NN];          // in-degree counts, then CSR cursor
__device__ int   g_rowptr[NN + 1];   // CSR row pointers (by dst)
__device__ int   g_bsum[256];        // per-block scan sums
__device__ int   g_eidx[EE];         // src node per CSR slot
__device__ float g_dinv[NN];
__device__ float g_hs1[(size_t)NN * DH_];    // (x @ W1) * dinv[row]
__device__ float g_agg1[(size_t)NN * DH_];   // layer-1 output (pre-relu)
__device__ float g_hs2[(size_t)NN * DOUT_];  // (relu(agg1) @ W2) * dinv[row]

// ---------------------------------------------------------------------------
// CSR construction
// ---------------------------------------------------------------------------
__global__ void k_zero_cnt(int n) {
    int i = blockIdx.x * blockDim.x + threadIdx.x;
    if (i < n) g_cnt[i] = 0;
}

__global__ void k_count(const int* __restrict__ dst, int e) {
    int i = blockIdx.x * blockDim.x + threadIdx.x;
    if (i < e) atomicAdd(&g_cnt[dst[i]], 1);
}

__global__ void k_dinv(int n) {
    int i = blockIdx.x * blockDim.x + threadIdx.x;
    if (i < n) g_dinv[i] = rsqrtf((float)g_cnt[i] + 1.0f);
}

__global__ void k_scanA(int n) {
    __shared__ int sh[32];
    int b = blockIdx.x;
    int i = b * 1024 + (int)threadIdx.x;
    int lane = threadIdx.x & 31, wid = threadIdx.x >> 5;
    int v = (i < n) ? g_cnt[i] : 0;
    int x = v;
#pragma unroll
    for (int o = 1; o < 32; o <<= 1) {
        int t = __shfl_up_sync(0xffffffffu, x, o);
        if (lane >= o) x += t;
    }
    if (lane == 31) sh[wid] = x;
    __syncthreads();
    if (wid == 0) {
        int y = sh[lane];
#pragma unroll
        for (int o = 1; o < 32; o <<= 1) {
            int t = __shfl_up_sync(0xffffffffu, y, o);
            if (lane >= o) y += t;
        }
        sh[lane] = y;
    }
    __syncthreads();
    int excl = x - v + (wid > 0 ? sh[wid - 1] : 0);
    if (i < n) g_rowptr[i] = excl;
    if (threadIdx.x == 1023) g_bsum[b] = excl + v;
}

__global__ void k_scanB(int nb) {
    __shared__ int sh[4];
    int lane = threadIdx.x & 31, wid = threadIdx.x >> 5;
    int v = ((int)threadIdx.x < nb) ? g_bsum[threadIdx.x] : 0;
    int x = v;
#pragma unroll
    for (int o = 1; o < 32; o <<= 1) {
        int t = __shfl_up_sync(0xffffffffu, x, o);
        if (lane >= o) x += t;
    }
    if (lane == 31) sh[wid] = x;
    __syncthreads();
    int add = 0;
#pragma unroll
    for (int w = 0; w < 4; w++) add += (w < wid) ? sh[w] : 0;
    if ((int)threadIdx.x < nb) g_bsum[threadIdx.x] = x - v + add;
}

__global__ void k_scanC(int n, int e) {
    int i = blockIdx.x * blockDim.x + threadIdx.x;
    if (i < n) {
        int r = g_rowptr[i] + g_bsum[i >> 10];
        g_rowptr[i] = r;
        g_cnt[i] = r;
    }
    if (i == 0) g_rowptr[n] = e;
}

__global__ void k_fill(const int* __restrict__ src, const int* __restrict__ dst, int e) {
    int i = blockIdx.x * blockDim.x + threadIdx.x;
    if (i < e) {
        int pos = atomicAdd(&g_cnt[dst[i]], 1);
        g_eidx[pos] = src[i];
    }
}

// ---------------------------------------------------------------------------
// GEMM: C[row, :] = (relu?)(A[row, :128]) @ W[128, DC] * dinv[row]
// ---------------------------------------------------------------------------
template <int DC, bool RELU>
__global__ void __launch_bounds__(256) k_gemm(const float* __restrict__ A,
                                              const float* __restrict__ W,
                                              float* __restrict__ C, int nrows) {
    __shared__ float As[64 * 128];

    constexpr int CG  = DC / 4;
    constexpr int RG  = 256 / CG;
    constexpr int RPT = 64 / RG;

    int row0 = blockIdx.x * 64;
    int rows = nrows - row0; if (rows > 64) rows = 64;

    for (int i = threadIdx.x; i < rows * 32; i += 256) {
        float4 v = ((const float4*)(A + (size_t)row0 * 128))[i];
        if (RELU) {
            v.x = fmaxf(v.x, 0.f); v.y = fmaxf(v.y, 0.f);
            v.z = fmaxf(v.z, 0.f); v.w = fmaxf(v.w, 0.f);
        }
        ((float4*)As)[i] = v;
    }
    __syncthreads();

    int tx = threadIdx.x % CG;
    int ty = threadIdx.x / CG;
    int r0 = ty * RPT;

    float acc[RPT][4];
#pragma unroll
    for (int r = 0; r < RPT; r++) { acc[r][0] = acc[r][1] = acc[r][2] = acc[r][3] = 0.f; }

    const float4* W4 = (const float4*)W;
#pragma unroll 4
    for (int k = 0; k < 128; k++) {
        float4 w = __ldg(&W4[k * CG + tx]);
#pragma unroll
        for (int r = 0; r < RPT; r++) {
            float a = As[(r0 + r) * 128 + k];
            acc[r][0] = fmaf(a, w.x, acc[r][0]);
            acc[r][1] = fmaf(a, w.y, acc[r][1]);
            acc[r][2] = fmaf(a, w.z, acc[r][2]);
            acc[r][3] = fmaf(a, w.w, acc[r][3]);
        }
    }

#pragma unroll
    for (int r = 0; r < RPT; r++) {
        int row = row0 + r0 + r;
        if (row < nrows) {
            float dv = g_dinv[row];
            float4 o = make_float4(acc[r][0] * dv, acc[r][1] * dv,
                                   acc[r][2] * dv, acc[r][3] * dv);
            ((float4*)(C + (size_t)row * DC))[tx] = o;
        }
    }
}

// ---------------------------------------------------------------------------
// Pull aggregation, batched-MLP form:
// per 8-edge batch: ONE coalesced index load (lanes 0..7) + shfl broadcast,
// then 8 independent __ldg gathers; predicated tail (no serial chains).
// ---------------------------------------------------------------------------
__global__ void k_agg128(const float* __restrict__ hs, const float* __restrict__ b,
                         float* __restrict__ out, int n) {
    int node = (blockIdx.x * blockDim.x + threadIdx.x) >> 5;
    int lane = threadIdx.x & 31;
    if (node >= n) return;
    int beg = g_rowptr[node], end = g_rowptr[node + 1];
    const float4* h4 = (const float4*)hs;

    float4 acc = __ldg(&h4[(size_t)node * 32 + lane]);   // self

    for (int e0 = beg; e0 < end; e0 += 8) {
        int m = end - e0; if (m > 8) m = 8;
        int ii = e0 + (lane & 7);
        int idxv = __ldg(&g_eidx[ii < end ? ii : end - 1]);
        float4 v[8];
#pragma unroll
        for (int t = 0; t < 8; t++) {
            int s = __shfl_sync(0xffffffffu, idxv, t);
            v[t] = __ldg(&h4[(size_t)s * 32 + lane]);
        }
#pragma unroll
        for (int t = 0; t < 8; t++) {
            if (t < m) {
                acc.x += v[t].x; acc.y += v[t].y;
                acc.z += v[t].z; acc.w += v[t].w;
            }
        }
    }

    float dv = g_dinv[node];
    float4 bb = ((const float4*)b)[lane];
    acc.x = fmaf(acc.x, dv, bb.x);
    acc.y = fmaf(acc.y, dv, bb.y);
    acc.z = fmaf(acc.z, dv, bb.z);
    acc.w = fmaf(acc.w, dv, bb.w);
    *(float4*)(out + (size_t)node * 128 + lane * 4) = acc;
}

__global__ void k_agg64(const float* __restrict__ hs, const float* __restrict__ b,
                        float* __restrict__ out, int n) {
    int node = (blockIdx.x * blockDim.x + threadIdx.x) >> 5;
    int lane = threadIdx.x & 31;
    if (node >= n) return;
    int beg = g_rowptr[node], end = g_rowptr[node + 1];
    const float2* h2 = (const float2*)hs;

    float2 acc = __ldg(&h2[(size_t)node * 32 + lane]);   // self

    for (int e0 = beg; e0 < end; e0 += 8) {
        int m = end - e0; if (m > 8) m = 8;
        int ii = e0 + (lane & 7);
        int idxv = __ldg(&g_eidx[ii < end ? ii : end - 1]);
        float2 v[8];
#pragma unroll
        for (int t = 0; t < 8; t++) {
            int s = __shfl_sync(0xffffffffu, idxv, t);
            v[t] = __ldg(&h2[(size_t)s * 32 + lane]);
        }
#pragma unroll
        for (int t = 0; t < 8; t++) {
            if (t < m) { acc.x += v[t].x; acc.y += v[t].y; }
        }
    }

    float dv = g_dinv[node];
    float2 bb = ((const float2*)b)[lane];
    acc.x = fmaf(acc.x, dv, bb.x);
    acc.y = fmaf(acc.y, dv, bb.y);
    *(float2*)(out + (size_t)node * 64 + lane * 2) = acc;
}

// ---------------------------------------------------------------------------
extern "C" void kernel_launch(void* const* d_in, const int* in_sizes, int n_in,
                              void* d_out, int out_size) {
    const float* x  = (const float*)d_in[0];
    const int*   ei = (const int*)d_in[1];
    const float* W1 = (const float*)d_in[2];
    const float* b1 = (const float*)d_in[3];
    const float* W2 = (const float*)d_in[4];
    const float* b2 = (const float*)d_in[5];
    float* out = (float*)d_out;

    int n = in_sizes[0] / DIN_;
    int e = in_sizes[1] / 2;
    const int* src = ei;
    const int* dst = ei + e;

    const int T = 256;
    int nb = (n + 1023) / 1024;

    // launch 0-2
    k_zero_cnt<<<(n + T - 1) / T, T>>>(n);
    k_count<<<(e + T - 1) / T, T>>>(dst, e);
    k_dinv<<<(n + T - 1) / T, T>>>(n);

    // launch 3: PROBE — k_agg128 on previous-replay state (deterministic; its
    // output g_agg1 is fully overwritten by the real agg below). Exists solely
    // so ncu (which captures launch index 3) profiles the aggregation kernel.
    k_agg128<<<(n * 32 + T - 1) / T, T>>>(g_hs1, b1, g_agg1, n);

    // launch 4: gemm1
    k_gemm<128, false><<<(n + 63) / 64, 256>>>(x, W1, g_hs1, n);

    // launch 5-8: CSR build
    k_scanA<<<nb, 1024>>>(n);
    k_scanB<<<1, 128>>>(nb);
    k_scanC<<<(n + T - 1) / T, T>>>(n, e);
    k_fill<<<(e + T - 1) / T, T>>>(src, dst, e);

    // launch 9: real layer-1 aggregation
    k_agg128<<<(n * 32 + T - 1) / T, T>>>(g_hs1, b1, g_agg1, n);

    // launch 10-11: layer 2
    k_gemm<64, true><<<(n + 63) / 64, 256>>>(g_agg1, W2, g_hs2, n);
    k_agg64<<<(n * 32 + T - 1) / T, T>>>(g_hs2, b2, out, n);
}